// round 10
// baseline (speedup 1.0000x reference)
#include <cuda_runtime.h>
#include <math.h>

#define MAXB 4096
__device__ float    g_seg_bce[MAXB];   // zero-init at module load; last block re-zeroes
__device__ float    g_seg_cnt[MAXB];
__device__ unsigned g_ticket;          // zero-init; last block resets

__device__ __forceinline__ float bce_fast(float p, float t) {
    float lp = fmaxf(__logf(p),        -100.0f);   // __logf(0) = -inf -> -100
    float lq = fmaxf(__logf(1.0f - p), -100.0f);
    return -(t * lp + (1.0f - t) * lq);
}

// reduce-and-commit for one coalesced chunk; warp-uniform entry
__device__ __forceinline__ void commit_chunk(bool valid, unsigned act,
                                             const float4& p4, const float4& t4,
                                             const int4& s4, const int4& k4) {
    const unsigned FULL = 0xffffffffu;
    float m0=0,m1=0,m2=0,m3=0, b0=0,b1=0,b2=0,b3=0;
    if (valid) {
        m0 = (float)k4.x; m1 = (float)k4.y; m2 = (float)k4.z; m3 = (float)k4.w;
        b0 = bce_fast(p4.x * m0, t4.x);
        b1 = bce_fast(p4.y * m1, t4.y);
        b2 = bce_fast(p4.z * m2, t4.z);
        b3 = bce_fast(p4.w * m3, t4.w);
    }
    int wlo = __shfl_sync(FULL, s4.x, 0);
    int whi = __shfl_sync(FULL, s4.w, 31);
    if (act == FULL && wlo == whi) {
        float b = (b0 + b1) + (b2 + b3);
        float m = (m0 + m1) + (m2 + m3);
        #pragma unroll
        for (int o = 16; o; o >>= 1) {
            b += __shfl_down_sync(FULL, b, o);
            m += __shfl_down_sync(FULL, m, o);
        }
        if ((threadIdx.x & 31) == 0) {
            atomicAdd(&g_seg_bce[wlo], b);
            atomicAdd(&g_seg_cnt[wlo], m);
        }
    } else if (valid) {
        if (s4.x == s4.w) {
            atomicAdd(&g_seg_bce[s4.x], (b0 + b1) + (b2 + b3));
            atomicAdd(&g_seg_cnt[s4.x], (m0 + m1) + (m2 + m3));
        } else {
            atomicAdd(&g_seg_bce[s4.x], b0); atomicAdd(&g_seg_cnt[s4.x], m0);
            atomicAdd(&g_seg_bce[s4.y], b1); atomicAdd(&g_seg_cnt[s4.y], m1);
            atomicAdd(&g_seg_bce[s4.z], b2); atomicAdd(&g_seg_cnt[s4.z], m2);
            atomicAdd(&g_seg_bce[s4.w], b3); atomicAdd(&g_seg_cnt[s4.w], m3);
        }
    }
}

__global__ void __launch_bounds__(256) fused_persistent_kernel(
        const float* __restrict__ pred,
        const float* __restrict__ tgt,
        const int*   __restrict__ batch,
        const int*   __restrict__ mask,
        const float* __restrict__ sat_p,
        const float* __restrict__ sat_t,
        float*       __restrict__ out,
        int n4, int N, int B, float l1)
{
    const unsigned FULL = 0xffffffffu;
    const float4* pred4  = (const float4*)pred;
    const float4* tgt4   = (const float4*)tgt;
    const int4*   batch4 = (const int4*)batch;
    const int4*   mask4  = (const int4*)mask;

    // ---- persistent node phase: 2 block-strided chunks per loop iteration ----
    int stride = gridDim.x * blockDim.x * 2;
    for (int base = blockIdx.x * (int)blockDim.x * 2 + threadIdx.x;
         base < n4; base += stride) {
        int gA = base;
        int gB = base + blockDim.x;
        bool vA = (gA < n4);               // always true given loop condition
        bool vB = (gB < n4);
        unsigned actA = __ballot_sync(FULL, vA);
        unsigned actB = __ballot_sync(FULL, vB);

        // front-batch all loads of both chunks (8 LDG.128 in flight)
        float4 pA = {}, tA = {}; int4 sA = {}, kA = {};
        float4 pB = {}, tB = {}; int4 sB = {}, kB = {};
        if (vA) { pA = __ldcs(&pred4[gA]); tA = __ldcs(&tgt4[gA]);
                  sA = __ldcs(&batch4[gA]); kA = __ldcs(&mask4[gA]); }
        if (vB) { pB = __ldcs(&pred4[gB]); tB = __ldcs(&tgt4[gB]);
                  sB = __ldcs(&batch4[gB]); kB = __ldcs(&mask4[gB]); }

        commit_chunk(vA, actA, pA, tA, sA, kA);
        if (actB) commit_chunk(vB, actB, pB, tB, sB, kB);
    }

    // scalar tail (N % 4) — block 0
    int tail = N - (n4 << 2);
    if (tail > 0 && blockIdx.x == 0 && (int)threadIdx.x < tail) {
        int j = (n4 << 2) + threadIdx.x;
        float mm = (float)mask[j];
        atomicAdd(&g_seg_bce[batch[j]], bce_fast(pred[j] * mm, tgt[j]));
        atomicAdd(&g_seg_cnt[batch[j]], mm);
    }

    // ---- ticket (592 CTAs; release-atomic, no per-block L1 flush) ----
    __shared__ int sh_last;
    __shared__ float sh[8];
    __syncthreads();
    if (threadIdx.x == 0) {
        unsigned t;
        asm volatile("atom.add.release.gpu.global.u32 %0, [%1], 1;"
                     : "=r"(t) : "l"(&g_ticket) : "memory");
        sh_last = (t == (unsigned)gridDim.x - 1u) ? 1 : 0;
    }
    __syncthreads();
    if (!sh_last) return;

    // ---- last block only: acquire + epilogue ----
    asm volatile("fence.acq_rel.gpu;" ::: "memory");

    float acc = 0.0f;
    for (int j = threadIdx.x; j < B; j += blockDim.x) {
        float c  = __ldcg(&g_seg_cnt[j]);
        float sb = __ldcg(&g_seg_bce[j]);
        acc += (c > 0.0f) ? (sb / fmaxf(c, 1.0f)) : 0.0f;
        acc += bce_fast(sat_p[j], sat_t[j]) * (l1 / (float)B);
        g_seg_cnt[j] = 0.0f;               // re-zero for next graph replay
        g_seg_bce[j] = 0.0f;
    }
    #pragma unroll
    for (int o = 16; o; o >>= 1) acc += __shfl_down_sync(FULL, acc, o);
    int lane = threadIdx.x & 31, wid = threadIdx.x >> 5;
    if (lane == 0) sh[wid] = acc;
    __syncthreads();
    if (wid == 0) {
        acc = (lane < (int)(blockDim.x >> 5)) ? sh[lane] : 0.0f;
        #pragma unroll
        for (int o = 16; o; o >>= 1) acc += __shfl_down_sync(FULL, acc, o);
        if (lane == 0) {
            out[0] = acc;
            atomicExch(&g_ticket, 0u);     // reset for next replay
        }
    }
}

extern "C" void kernel_launch(void* const* d_in, const int* in_sizes, int n_in,
                              void* d_out, int out_size) {
    const float* y_mus_pred = (const float*)d_in[0];
    const float* y_mus      = (const float*)d_in[1];
    const float* y_sat_pred = (const float*)d_in[2];
    const float* y_sat      = (const float*)d_in[3];
    const int*   batch      = (const int*)  d_in[4];
    const int*   mask       = (const int*)  d_in[5];
    int N = in_sizes[0];
    int B = in_sizes[2];
    float L1 = 1.0f / 50.0f;

    int n4 = N >> 2;
    // 4 CTAs/SM: guaranteed single resident wave even at ~56 regs
    int blocks = 148 * 4;
    int max_blocks = (n4 + 511) / 512;
    if (max_blocks < 1) max_blocks = 1;
    if (blocks > max_blocks) blocks = max_blocks;

    fused_persistent_kernel<<<blocks, 256>>>(y_mus_pred, y_mus, batch, mask,
                                             y_sat_pred, y_sat, (float*)d_out,
                                             n4, N, B, L1);
}

// round 11
// speedup vs baseline: 1.4245x; 1.4245x over previous
#include <cuda_runtime.h>
#include <math.h>

#define MAXB 4096
__device__ float g_seg_bce[MAXB];   // zero-init at module load; finalize re-zeroes
__device__ float g_seg_cnt[MAXB];

__device__ __forceinline__ float bce_fast(float p, float t) {
    float lp = fmaxf(__logf(p),        -100.0f);   // __logf(0) = -inf -> -100
    float lq = fmaxf(__logf(1.0f - p), -100.0f);
    return -(t * lp + (1.0f - t) * lq);
}

// ---- node kernel: proven R5 shape (MLP_p1=4, coalesced LDG.128, .cs) ----
__global__ void __launch_bounds__(256) node_kernel(
        const float4* __restrict__ pred4,
        const float4* __restrict__ tgt4,
        const int4*   __restrict__ batch4,
        const int4*   __restrict__ mask4,
        float*        __restrict__ out,
        int n4)
{
    const unsigned FULL = 0xffffffffu;
    int i = blockIdx.x * blockDim.x + threadIdx.x;

    // initialize output accumulator (graph edge orders this before finalize's adds)
    if (i == 0) out[0] = 0.0f;

    if (i >= n4) return;

    float4 p4 = __ldcs(&pred4[i]);
    float4 t4 = __ldcs(&tgt4[i]);
    int4   s4 = __ldcs(&batch4[i]);
    int4   k4 = __ldcs(&mask4[i]);

    float m0 = (float)k4.x, m1 = (float)k4.y, m2 = (float)k4.z, m3 = (float)k4.w;
    float b0 = bce_fast(p4.x * m0, t4.x);
    float b1 = bce_fast(p4.y * m1, t4.y);
    float b2 = bce_fast(p4.z * m2, t4.z);
    float b3 = bce_fast(p4.w * m3, t4.w);

    unsigned act = __activemask();
    if (act == FULL) {
        int wlo = __shfl_sync(FULL, s4.x, 0);
        int whi = __shfl_sync(FULL, s4.w, 31);
        if (wlo == whi) {
            // 128 contiguous nodes in one segment (batch sorted)
            float b = (b0 + b1) + (b2 + b3);
            float m = (m0 + m1) + (m2 + m3);
            #pragma unroll
            for (int o = 16; o; o >>= 1) {
                b += __shfl_down_sync(FULL, b, o);
                m += __shfl_down_sync(FULL, m, o);
            }
            if ((threadIdx.x & 31) == 0) {
                atomicAdd(&g_seg_bce[wlo], b);
                atomicAdd(&g_seg_cnt[wlo], m);
            }
            return;
        }
    }
    if (s4.x == s4.w) {
        atomicAdd(&g_seg_bce[s4.x], (b0 + b1) + (b2 + b3));
        atomicAdd(&g_seg_cnt[s4.x], (m0 + m1) + (m2 + m3));
    } else {
        atomicAdd(&g_seg_bce[s4.x], b0); atomicAdd(&g_seg_cnt[s4.x], m0);
        atomicAdd(&g_seg_bce[s4.y], b1); atomicAdd(&g_seg_cnt[s4.y], m1);
        atomicAdd(&g_seg_bce[s4.z], b2); atomicAdd(&g_seg_cnt[s4.z], m2);
        atomicAdd(&g_seg_bce[s4.w], b3); atomicAdd(&g_seg_cnt[s4.w], m3);
    }
}

// scalar tail (N % 4)
__global__ void tail_kernel(const float* __restrict__ pred,
                            const float* __restrict__ tgt,
                            const int*   __restrict__ batch,
                            const int*   __restrict__ mask,
                            int start, int n)
{
    int i = start + blockIdx.x * blockDim.x + threadIdx.x;
    if (i >= n) return;
    float m = (float)mask[i];
    atomicAdd(&g_seg_bce[batch[i]], bce_fast(pred[i] * m, tgt[i]));
    atomicAdd(&g_seg_cnt[batch[i]], m);
}

// ---- finalize: 8 independent blocks, no ticket/fence; REDG into out[0] ----
__global__ void __launch_bounds__(256) finalize_kernel(
        const float* __restrict__ sat_p,
        const float* __restrict__ sat_t,
        float* __restrict__ out,
        int B, float l1)
{
    const unsigned FULL = 0xffffffffu;
    __shared__ float sh[8];

    float acc = 0.0f;
    for (int i = blockIdx.x * blockDim.x + threadIdx.x; i < B;
         i += gridDim.x * blockDim.x) {
        float c  = g_seg_cnt[i];
        float sb = g_seg_bce[i];
        acc += (c > 0.0f) ? (sb / fmaxf(c, 1.0f)) : 0.0f;
        acc += bce_fast(sat_p[i], sat_t[i]) * (l1 / (float)B);
        g_seg_cnt[i] = 0.0f;            // re-zero for next graph replay
        g_seg_bce[i] = 0.0f;
    }
    #pragma unroll
    for (int o = 16; o; o >>= 1) acc += __shfl_down_sync(FULL, acc, o);
    int lane = threadIdx.x & 31, wid = threadIdx.x >> 5;
    if (lane == 0) sh[wid] = acc;
    __syncthreads();
    if (wid == 0) {
        acc = (lane < (int)(blockDim.x >> 5)) ? sh[lane] : 0.0f;
        #pragma unroll
        for (int o = 16; o; o >>= 1) acc += __shfl_down_sync(FULL, acc, o);
        if (lane == 0) atomicAdd(out, acc);   // REDG, no return needed
    }
}

extern "C" void kernel_launch(void* const* d_in, const int* in_sizes, int n_in,
                              void* d_out, int out_size) {
    const float* y_mus_pred = (const float*)d_in[0];
    const float* y_mus      = (const float*)d_in[1];
    const float* y_sat_pred = (const float*)d_in[2];
    const float* y_sat      = (const float*)d_in[3];
    const int*   batch      = (const int*)  d_in[4];
    const int*   mask       = (const int*)  d_in[5];
    int N = in_sizes[0];
    int B = in_sizes[2];
    float L1 = 1.0f / 50.0f;

    int n4 = N >> 2;
    int blocks = (n4 + 255) / 256;
    if (blocks < 1) blocks = 1;
    node_kernel<<<blocks, 256>>>((const float4*)y_mus_pred,
                                 (const float4*)y_mus,
                                 (const int4*)batch,
                                 (const int4*)mask,
                                 (float*)d_out, n4);

    int tail_start = n4 << 2;
    if (tail_start < N) {
        tail_kernel<<<1, 256>>>(y_mus_pred, y_mus, batch, mask, tail_start, N);
    }

    finalize_kernel<<<8, 256>>>(y_sat_pred, y_sat, (float*)d_out, B, L1);
}

// round 12
// speedup vs baseline: 1.4292x; 1.0033x over previous
#include <cuda_runtime.h>
#include <math.h>

#define MAXB 4096
__device__ float g_seg_bce[MAXB];   // zero-init at module load; finalize re-zeroes
__device__ float g_seg_cnt[MAXB];

__device__ __forceinline__ float bce_fast(float p, float t) {
    float lp = fmaxf(__logf(p),        -100.0f);   // __logf(0) = -inf -> -100
    float lq = fmaxf(__logf(1.0f - p), -100.0f);
    return -(t * lp + (1.0f - t) * lq);
}

// ---- node kernel: proven R5 streaming shape + sat-BCE folded into block 0 ----
__global__ void __launch_bounds__(256) node_kernel(
        const float4* __restrict__ pred4,
        const float4* __restrict__ tgt4,
        const int4*   __restrict__ batch4,
        const int4*   __restrict__ mask4,
        const float*  __restrict__ sat_p,
        const float*  __restrict__ sat_t,
        float*        __restrict__ out,
        int n4, int B, float l1)
{
    const unsigned FULL = 0xffffffffu;

    // block 0: zero the output accumulator, then add the saturation term.
    // Overlaps with the main stream; finalize's REDGs are ordered after this
    // kernel by the graph edge.
    if (blockIdx.x == 0) {
        if (threadIdx.x == 0) out[0] = 0.0f;
        __syncthreads();
        float s = 0.0f;
        for (int j = threadIdx.x; j < B; j += blockDim.x)
            s += bce_fast(sat_p[j], sat_t[j]);
        s *= l1 / (float)B;
        #pragma unroll
        for (int o = 16; o; o >>= 1) s += __shfl_down_sync(FULL, s, o);
        if ((threadIdx.x & 31) == 0) atomicAdd(out, s);
    }

    int i = blockIdx.x * blockDim.x + threadIdx.x;
    if (i >= n4) return;

    float4 p4 = __ldcs(&pred4[i]);
    float4 t4 = __ldcs(&tgt4[i]);
    int4   s4 = __ldcs(&batch4[i]);
    int4   k4 = __ldcs(&mask4[i]);

    int   im = (k4.x + k4.y) + (k4.z + k4.w);       // mask count (ints)
    float m0 = (float)k4.x, m1 = (float)k4.y, m2 = (float)k4.z, m3 = (float)k4.w;
    float b0 = bce_fast(p4.x * m0, t4.x);
    float b1 = bce_fast(p4.y * m1, t4.y);
    float b2 = bce_fast(p4.z * m2, t4.z);
    float b3 = bce_fast(p4.w * m3, t4.w);

    unsigned act = __activemask();
    if (act == FULL) {
        int wlo = __shfl_sync(FULL, s4.x, 0);
        int whi = __shfl_sync(FULL, s4.w, 31);
        if (wlo == whi) {
            // 128 contiguous nodes in one segment (batch sorted)
            float b = (b0 + b1) + (b2 + b3);
            int  ws = __reduce_add_sync(FULL, im);   // single REDUX.SUM
            #pragma unroll
            for (int o = 16; o; o >>= 1)
                b += __shfl_down_sync(FULL, b, o);
            if ((threadIdx.x & 31) == 0) {
                atomicAdd(&g_seg_bce[wlo], b);
                atomicAdd(&g_seg_cnt[wlo], (float)ws);
            }
            return;
        }
    }
    if (s4.x == s4.w) {
        atomicAdd(&g_seg_bce[s4.x], (b0 + b1) + (b2 + b3));
        atomicAdd(&g_seg_cnt[s4.x], (float)im);
    } else {
        atomicAdd(&g_seg_bce[s4.x], b0); atomicAdd(&g_seg_cnt[s4.x], m0);
        atomicAdd(&g_seg_bce[s4.y], b1); atomicAdd(&g_seg_cnt[s4.y], m1);
        atomicAdd(&g_seg_bce[s4.z], b2); atomicAdd(&g_seg_cnt[s4.z], m2);
        atomicAdd(&g_seg_bce[s4.w], b3); atomicAdd(&g_seg_cnt[s4.w], m3);
    }
}

// scalar tail (N % 4)
__global__ void tail_kernel(const float* __restrict__ pred,
                            const float* __restrict__ tgt,
                            const int*   __restrict__ batch,
                            const int*   __restrict__ mask,
                            int start, int n)
{
    int i = start + blockIdx.x * blockDim.x + threadIdx.x;
    if (i >= n) return;
    float m = (float)mask[i];
    atomicAdd(&g_seg_bce[batch[i]], bce_fast(pred[i] * m, tgt[i]));
    atomicAdd(&g_seg_cnt[batch[i]], m);
}

// ---- finalize: only L2-resident g_seg data; 8 blocks, REDG into out ----
__global__ void __launch_bounds__(256) finalize_kernel(float* __restrict__ out, int B)
{
    const unsigned FULL = 0xffffffffu;
    __shared__ float sh[8];

    float acc = 0.0f;
    for (int i = blockIdx.x * blockDim.x + threadIdx.x; i < B;
         i += gridDim.x * blockDim.x) {
        float c  = g_seg_cnt[i];
        float sb = g_seg_bce[i];
        acc += (c > 0.0f) ? (sb / fmaxf(c, 1.0f)) : 0.0f;
        g_seg_cnt[i] = 0.0f;            // re-zero for next graph replay
        g_seg_bce[i] = 0.0f;
    }
    #pragma unroll
    for (int o = 16; o; o >>= 1) acc += __shfl_down_sync(FULL, acc, o);
    int lane = threadIdx.x & 31, wid = threadIdx.x >> 5;
    if (lane == 0) sh[wid] = acc;
    __syncthreads();
    if (wid == 0) {
        acc = (lane < (int)(blockDim.x >> 5)) ? sh[lane] : 0.0f;
        #pragma unroll
        for (int o = 16; o; o >>= 1) acc += __shfl_down_sync(FULL, acc, o);
        if (lane == 0) atomicAdd(out, acc);
    }
}

extern "C" void kernel_launch(void* const* d_in, const int* in_sizes, int n_in,
                              void* d_out, int out_size) {
    const float* y_mus_pred = (const float*)d_in[0];
    const float* y_mus      = (const float*)d_in[1];
    const float* y_sat_pred = (const float*)d_in[2];
    const float* y_sat      = (const float*)d_in[3];
    const int*   batch      = (const int*)  d_in[4];
    const int*   mask       = (const int*)  d_in[5];
    int N = in_sizes[0];
    int B = in_sizes[2];
    float L1 = 1.0f / 50.0f;

    int n4 = N >> 2;
    int blocks = (n4 + 255) / 256;
    if (blocks < 1) blocks = 1;
    node_kernel<<<blocks, 256>>>((const float4*)y_mus_pred,
                                 (const float4*)y_mus,
                                 (const int4*)batch,
                                 (const int4*)mask,
                                 y_sat_pred, y_sat,
                                 (float*)d_out, n4, B, L1);

    int tail_start = n4 << 2;
    if (tail_start < N) {
        tail_kernel<<<1, 256>>>(y_mus_pred, y_mus, batch, mask, tail_start, N);
    }

    finalize_kernel<<<8, 256>>>((float*)d_out, B);
}